// round 12
// baseline (speedup 1.0000x reference)
#include <cuda_runtime.h>
#include <cuda_bf16.h>
#include <cstdint>

#define EPSV 1e-6f

#define BB 8
#define HH 256
#define WW 256
#define CC 64
#define NPIX (BB*HH*WW)

// ---------------------------------------------------------------------------
// Scratch (static __device__ globals per harness rules)
// ---------------------------------------------------------------------------
__device__ __nv_bfloat16 g_t1b[(size_t)NPIX * 256];  // pw1 output (bf16)
__device__ __nv_bfloat16 g_yb [(size_t)NPIX * 128];  // gated dw out (bf16)
__device__ float g_x2[(size_t)NPIX * CC];            // stage-1 residual (fp32)
__device__ float g_part[4096 * 128];                 // GAP partials
__device__ float g_part2[64 * 128];                  // GAP stage-2 partials
__device__ float g_attn[BB * 128];                   // channel attention
// Transposed bf16 weights (n-major rows, k contiguous)
__device__ __align__(16) __nv_bfloat16 g_w1t[256*64];
__device__ __align__(16) __nv_bfloat16 g_w2t[64*128];
__device__ __align__(16) __nv_bfloat16 g_w3t[256*64];   // gate-interleaved rows
__device__ __align__(16) __nv_bfloat16 g_w4t[64*128];

// ---------------------------------------------------------------------------
// Helpers
// ---------------------------------------------------------------------------
__device__ __forceinline__ uint32_t smem_u32(const void* p){
    uint32_t a; asm("{ .reg .u64 t; cvta.to.shared.u64 t, %1; cvt.u32.u64 %0, t; }" : "=r"(a) : "l"(p)); return a;
}
__device__ __forceinline__ void ldsm4(uint32_t* r, uint32_t addr){
    asm volatile("ldmatrix.sync.aligned.m8n8.x4.shared.b16 {%0,%1,%2,%3}, [%4];"
        : "=r"(r[0]), "=r"(r[1]), "=r"(r[2]), "=r"(r[3]) : "r"(addr));
}
__device__ __forceinline__ void ldsm2(uint32_t* r, uint32_t addr){
    asm volatile("ldmatrix.sync.aligned.m8n8.x2.shared.b16 {%0,%1}, [%2];"
        : "=r"(r[0]), "=r"(r[1]) : "r"(addr));
}
__device__ __forceinline__ void mma16816(float* d, const uint32_t* a, const uint32_t* b){
    asm volatile("mma.sync.aligned.m16n8k16.row.col.f32.bf16.bf16.f32 "
        "{%0,%1,%2,%3}, {%4,%5,%6,%7}, {%8,%9}, {%0,%1,%2,%3};"
        : "+f"(d[0]), "+f"(d[1]), "+f"(d[2]), "+f"(d[3])
        : "r"(a[0]), "r"(a[1]), "r"(a[2]), "r"(a[3]), "r"(b[0]), "r"(b[1]));
}
__device__ __forceinline__ uint32_t bfpack(float a, float b){
    __nv_bfloat162 h = __floats2bfloat162_rn(a, b);
    return *(uint32_t*)&h;
}
__device__ __forceinline__ float2 bfunpk(uint32_t u){
    __nv_bfloat162 h = *(__nv_bfloat162*)&u;
    return __bfloat1622float2(h);
}
__device__ __forceinline__ void st_bf2s(char* p, float a, float b){
    *(__nv_bfloat162*)p = __floats2bfloat162_rn(a, b);
}

// ---------------------------------------------------------------------------
// K0: weight prep — transposed bf16 (n-major)
// ---------------------------------------------------------------------------
__global__ void k0_prep(const float* __restrict__ w1, const float* __restrict__ w2,
                        const float* __restrict__ w3, const float* __restrict__ w4)
{
    int idx = blockIdx.x * 256 + threadIdx.x;     // 192*256 = 49152
    if (idx < 16384){                             // w1t [256 n][64 k]
        int n = idx >> 6, k = idx & 63;
        g_w1t[n*64 + k] = __float2bfloat16(w1[k*256 + n]);
    } else if (idx < 24576){                      // w2t [64 n][128 k]
        int i = idx - 16384; int n = i >> 7, k = i & 127;
        g_w2t[n*128 + k] = __float2bfloat16(w2[k*64 + n]);
    } else if (idx < 40960){                      // w3t interleaved [256 n][64 k]
        int i = idx - 24576; int n = i >> 6, k = i & 63;
        g_w3t[n*64 + k] = __float2bfloat16(w3[k*256 + (n & 1)*128 + (n >> 1)]);
    } else {                                      // w4t [64 n][128 k]
        int i = idx - 40960; int n = i >> 7, k = i & 127;
        g_w4t[n*128 + k] = __float2bfloat16(w4[k*64 + n]);
    }
}

// ---------------------------------------------------------------------------
// K1: LN1 + pw1 (64 -> 256) via mma.sync. 128 px/block, 256 threads (8 warps).
// Epilogue staged through per-warp smem for fully coalesced uint4 stores.
// ---------------------------------------------------------------------------
#define K1_SW_OFF   18432
#define K1_PAR_OFF  55296
#define K1_STG_OFF  56832
#define K1_SMEM     67072

__global__ void __launch_bounds__(256) k1_ln_pw1(
    const float* __restrict__ x, const float* __restrict__ g1,
    const float* __restrict__ b1v, const float* __restrict__ bias)
{
    extern __shared__ char smem[];
    uint32_t sb = smem_u32(smem);
    int tid = threadIdx.x, wid = tid >> 5, lane = tid & 31;
    float* sBias = (float*)(smem + K1_PAR_OFF);   // 256
    float* sG  = sBias + 256;                     // 64
    float* sBe = sG + 64;                         // 64

    {
        const uint4* src = (const uint4*)(g_w1t + tid*64);
        uint4* dst = (uint4*)(smem + K1_SW_OFF + tid*144);
        #pragma unroll
        for (int q = 0; q < 8; q++) dst[q] = src[q];
    }
    sBias[tid] = bias[tid];
    if (tid < 64){ sG[tid] = g1[tid]; sBe[tid] = b1v[tid]; }
    __syncthreads();

    size_t P0 = (size_t)blockIdx.x * 128;
    {   // LN: 2 threads per pixel
        int px = tid >> 1, half = tid & 1;
        const float4* xp = (const float4*)(x + (P0 + px) * 64 + half * 32);
        float4 v[8];
        #pragma unroll
        for (int q = 0; q < 8; q++) v[q] = xp[q];
        float s = 0.f, ss = 0.f;
        #pragma unroll
        for (int q = 0; q < 8; q++){
            float4 t = v[q];
            s += t.x + t.y + t.z + t.w;
            ss = fmaf(t.x,t.x, fmaf(t.y,t.y, fmaf(t.z,t.z, fmaf(t.w,t.w, ss))));
        }
        s  += __shfl_xor_sync(0xffffffffu, s, 1);
        ss += __shfl_xor_sync(0xffffffffu, ss, 1);
        float mean = s * (1.f/64.f);
        float var  = fmaf(-mean, mean, ss * (1.f/64.f));
        float rstd = rsqrtf(var + EPSV);
        char* dstrow = smem + px*144 + half*64;
        #pragma unroll
        for (int g = 0; g < 4; g++){
            float4 va = v[2*g], vb = v[2*g+1];
            int c = half*32 + g*8;
            float f0 = fmaf((va.x-mean)*rstd, sG[c+0], sBe[c+0]);
            float f1 = fmaf((va.y-mean)*rstd, sG[c+1], sBe[c+1]);
            float f2 = fmaf((va.z-mean)*rstd, sG[c+2], sBe[c+2]);
            float f3 = fmaf((va.w-mean)*rstd, sG[c+3], sBe[c+3]);
            float f4 = fmaf((vb.x-mean)*rstd, sG[c+4], sBe[c+4]);
            float f5 = fmaf((vb.y-mean)*rstd, sG[c+5], sBe[c+5]);
            float f6 = fmaf((vb.z-mean)*rstd, sG[c+6], sBe[c+6]);
            float f7 = fmaf((vb.w-mean)*rstd, sG[c+7], sBe[c+7]);
            *(uint4*)(dstrow + g*16) = make_uint4(bfpack(f0,f1), bfpack(f2,f3),
                                                  bfpack(f4,f5), bfpack(f6,f7));
        }
    }
    __syncthreads();

    int ns = wid * 32;
    int br = lane & 7, bg = (lane >> 3) & 1;
    uint32_t bfr[4][4][2];
    #pragma unroll
    for (int nt = 0; nt < 4; nt++)
        #pragma unroll
        for (int kt = 0; kt < 4; kt++)
            ldsm2(bfr[nt][kt], sb + K1_SW_OFF + (ns + nt*8 + br)*144 + bg*16 + kt*32);

    int ag = lane >> 3, ar = lane & 7;
    uint32_t abase = sb + (ar + (ag & 1)*8)*144 + (ag >> 1)*16;
    char* wb = smem + K1_STG_OFF + wid*1280;    // 16 rows x 80B
    int rl = lane >> 2, cl = (lane & 3)*2;
    #pragma unroll 1
    for (int mt = 0; mt < 8; mt++){
        uint32_t af[4][4];
        #pragma unroll
        for (int kt = 0; kt < 4; kt++) ldsm4(af[kt], abase + mt*2304 + kt*32);
        float acc[4][4];
        #pragma unroll
        for (int nt = 0; nt < 4; nt++){ acc[nt][0]=0.f; acc[nt][1]=0.f; acc[nt][2]=0.f; acc[nt][3]=0.f; }
        #pragma unroll
        for (int kt = 0; kt < 4; kt++)
            #pragma unroll
            for (int nt = 0; nt < 4; nt++)
                mma16816(acc[nt], af[kt], bfr[nt][kt]);
        // stage fragment in per-warp smem (conflict-free), then coalesced store
        #pragma unroll
        for (int nt = 0; nt < 4; nt++){
            int c = cl + nt*8;
            int cg = ns + c;
            st_bf2s(wb + rl*80 + c*2,     acc[nt][0] + sBias[cg], acc[nt][1] + sBias[cg+1]);
            st_bf2s(wb + (rl+8)*80 + c*2, acc[nt][2] + sBias[cg], acc[nt][3] + sBias[cg+1]);
        }
        __syncwarp();
        #pragma unroll
        for (int p = 0; p < 2; p++){
            int idx = p*32 + lane;
            int row = idx >> 2, part = idx & 3;
            uint4 v = *(uint4*)(wb + row*80 + part*16);
            *(uint4*)((char*)g_t1b + (((P0 + mt*16 + row)*256) + ns + part*8)*2) = v;
        }
        __syncwarp();
    }
}

// ---------------------------------------------------------------------------
// K2: depthwise 3x3 + SimpleGate + GAP partials (bf16 I/O)
// 2 output rows per block, 4-row window, manual 1-col prefetch.
// grid = 8*128*2 = 2048 blocks, 128 threads: seg = tid>>6 (64-px w-seg),
// c2 = tid&63 (channel pair; half0 = ch/ch+1, half1 = ch+128/ch+129)
// ---------------------------------------------------------------------------
__global__ void __launch_bounds__(128) k2_dw_gate(const float* __restrict__ dww, const float* __restrict__ dwb)
{
    int blk = blockIdx.x;             // b*256 + hp*2 + wh
    int b   = blk >> 8;
    int rem = blk & 255;
    int hp  = rem >> 1;
    int wh  = rem & 1;
    int h   = hp << 1;                // even output row; block does h and h+1
    int seg = threadIdx.x >> 6;
    int c2  = threadIdx.x & 63;
    int ch  = c2 * 2;
    int w0  = wh*128 + seg*64;

    float2 wt0[9], wt1[9];
    #pragma unroll
    for (int i = 0; i < 9; i++){
        wt0[i] = make_float2(dww[i*256 + ch],       dww[i*256 + ch + 1]);
        wt1[i] = make_float2(dww[i*256 + 128 + ch], dww[i*256 + 128 + ch + 1]);
    }
    float2 bc0 = make_float2(dwb[ch], dwb[ch+1]);
    float2 bc1 = make_float2(dwb[128+ch], dwb[128+ch+1]);

    const __nv_bfloat162* img = (const __nv_bfloat162*)g_t1b;
    size_t rowb = (size_t)(b*256 + h) * 256;   // pixel index of row h start
    bool vm = (h > 0), vp = (h < 254);         // row h-1 / row h+2 validity
    size_t rA = rowb - 256, rB = rowb, rC = rowb + 256, rD = rowb + 512;
    const float2 Z = make_float2(0.f, 0.f);
    #define L0(rr, wc) __bfloat1622float2(img[((rr) + (size_t)(wc))*128 + c2])
    #define L1(rr, wc) __bfloat1622float2(img[((rr) + (size_t)(wc))*128 + 64 + c2])

    float2 a0[4][3], a1[4][3];   // [row 0..3][wpos: 0=w-1,1=w,2=w+1]
    {
        int wm = w0 - 1; bool v = (wm >= 0);
        a0[0][0] = (vm && v) ? L0(rA, wm) : Z;
        a0[1][0] =  v        ? L0(rB, wm) : Z;
        a0[2][0] =  v        ? L0(rC, wm) : Z;
        a0[3][0] = (vp && v) ? L0(rD, wm) : Z;
        a1[0][0] = (vm && v) ? L1(rA, wm) : Z;
        a1[1][0] =  v        ? L1(rB, wm) : Z;
        a1[2][0] =  v        ? L1(rC, wm) : Z;
        a1[3][0] = (vp && v) ? L1(rD, wm) : Z;

        a0[0][1] = vm ? L0(rA, w0) : Z;
        a0[1][1] =      L0(rB, w0);
        a0[2][1] =      L0(rC, w0);
        a0[3][1] = vp ? L0(rD, w0) : Z;
        a1[0][1] = vm ? L1(rA, w0) : Z;
        a1[1][1] =      L1(rB, w0);
        a1[2][1] =      L1(rC, w0);
        a1[3][1] = vp ? L1(rD, w0) : Z;

        int wq = w0 + 1;              // always < 256 (w0 <= 192)
        a0[0][2] = vm ? L0(rA, wq) : Z;
        a0[1][2] =      L0(rB, wq);
        a0[2][2] =      L0(rC, wq);
        a0[3][2] = vp ? L0(rD, wq) : Z;
        a1[0][2] = vm ? L1(rA, wq) : Z;
        a1[1][2] =      L1(rB, wq);
        a1[2][2] =      L1(rC, wq);
        a1[3][2] = vp ? L1(rD, wq) : Z;
    }

    __nv_bfloat162* yrow = (__nv_bfloat162*)g_yb;
    float2 gap = Z;
    for (int w = w0; w < w0 + 64; w++){
        // prefetch column w+2 (overlaps the FMA work below)
        int wf = w + 2; bool vf = (wf < 256);
        float2 tA0 = (vm && vf) ? L0(rA, wf) : Z;
        float2 tB0 =  vf        ? L0(rB, wf) : Z;
        float2 tC0 =  vf        ? L0(rC, wf) : Z;
        float2 tD0 = (vp && vf) ? L0(rD, wf) : Z;
        float2 tA1 = (vm && vf) ? L1(rA, wf) : Z;
        float2 tB1 =  vf        ? L1(rB, wf) : Z;
        float2 tC1 =  vf        ? L1(rC, wf) : Z;
        float2 tD1 = (vp && vf) ? L1(rD, wf) : Z;

        float2 p0 = bc0, p1 = bc1;   // output row h     (rows 0..2)
        float2 q0 = bc0, q1 = bc1;   // output row h+1   (rows 1..3)
        #pragma unroll
        for (int rr = 0; rr < 3; rr++){
            #pragma unroll
            for (int ww = 0; ww < 3; ww++){
                int i = rr*3 + ww;
                p0.x = fmaf(a0[rr  ][ww].x, wt0[i].x, p0.x); p0.y = fmaf(a0[rr  ][ww].y, wt0[i].y, p0.y);
                p1.x = fmaf(a1[rr  ][ww].x, wt1[i].x, p1.x); p1.y = fmaf(a1[rr  ][ww].y, wt1[i].y, p1.y);
                q0.x = fmaf(a0[rr+1][ww].x, wt0[i].x, q0.x); q0.y = fmaf(a0[rr+1][ww].y, wt0[i].y, q0.y);
                q1.x = fmaf(a1[rr+1][ww].x, wt1[i].x, q1.x); q1.y = fmaf(a1[rr+1][ww].y, wt1[i].y, q1.y);
            }
        }
        float2 yA = make_float2(p0.x * p1.x, p0.y * p1.y);
        float2 yB = make_float2(q0.x * q1.x, q0.y * q1.y);
        yrow[(rB + (size_t)w)*64 + c2] = __floats2bfloat162_rn(yA.x, yA.y);
        yrow[(rC + (size_t)w)*64 + c2] = __floats2bfloat162_rn(yB.x, yB.y);
        gap.x += yA.x + yB.x;
        gap.y += yA.y + yB.y;
        #pragma unroll
        for (int rr = 0; rr < 4; rr++){
            a0[rr][0] = a0[rr][1]; a0[rr][1] = a0[rr][2];
            a1[rr][0] = a1[rr][1]; a1[rr][1] = a1[rr][2];
        }
        a0[0][2] = tA0; a0[1][2] = tB0; a0[2][2] = tC0; a0[3][2] = tD0;
        a1[0][2] = tA1; a1[1][2] = tB1; a1[2][2] = tC1; a1[3][2] = tD1;
    }
    int pid = blk*2 + seg;            // 0..4095; image b owns [b*512, b*512+512)
    g_part[(size_t)pid*128 + ch]     = gap.x;
    g_part[(size_t)pid*128 + ch + 1] = gap.y;
    #undef L0
    #undef L1
}

// ---------------------------------------------------------------------------
// K3a: GAP partial reduce (64 blocks x 128 threads, 64 rows each)
// ---------------------------------------------------------------------------
__global__ void __launch_bounds__(128) k3a_reduce()
{
    int blk = blockIdx.x;             // rows blk*64 .. blk*64+63
    int c = threadIdx.x;
    const float* p = g_part + (size_t)blk * 64 * 128 + c;
    float s = 0.f;
    #pragma unroll 16
    for (int i = 0; i < 64; i++) s += p[(size_t)i * 128];
    g_part2[blk*128 + c] = s;
}

// ---------------------------------------------------------------------------
// K3b: final GAP reduce + SCA
// ---------------------------------------------------------------------------
__global__ void k3b_sca(const float* __restrict__ scaw, const float* __restrict__ scab)
{
    __shared__ float smn[128];
    int b = blockIdx.x, c = threadIdx.x;
    float s = 0.f;
    #pragma unroll
    for (int i = 0; i < 8; i++) s += g_part2[(b*8 + i)*128 + c];
    smn[c] = s * (1.f / 65536.f);
    __syncthreads();
    float a = scab[c];
    #pragma unroll 8
    for (int k = 0; k < 128; k++) a = fmaf(smn[k], scaw[k*128 + c], a);
    g_attn[b*128 + c] = a;
}

// ---------------------------------------------------------------------------
// K4a: (y*attn) -> pw2 (128 -> 64) -> x2 = x + .*beta. mma.sync, warp n-slice 8.
// ---------------------------------------------------------------------------
#define K4A_SW_OFF  34816
#define K4A_PAR_OFF 52224
#define K4A_SMEM    53248

__global__ void __launch_bounds__(256) k4a_att_pw2(
    const float* __restrict__ x, const float* __restrict__ b2v, const float* __restrict__ beta)
{
    extern __shared__ char smem[];
    uint32_t sb = smem_u32(smem);
    int tid = threadIdx.x, wid = tid >> 5, lane = tid & 31;
    float* sAttn = (float*)(smem + K4A_PAR_OFF);  // 128
    float* sB2   = sAttn + 128;                   // 64
    float* sBeta = sB2 + 64;                      // 64
    int b = blockIdx.x >> 9;

    {
        int row = tid >> 2, part = tid & 3;
        const uint4* src = (const uint4*)(g_w2t + row*128 + part*32);
        uint4* dst = (uint4*)(smem + K4A_SW_OFF + row*272 + part*64);
        #pragma unroll
        for (int q = 0; q < 4; q++) dst[q] = src[q];
    }
    if (tid < 128) sAttn[tid] = g_attn[b*128 + tid];
    else if (tid < 192) sB2[tid-128] = b2v[tid-128];
    else sBeta[tid-192] = beta[tid-192];
    __syncthreads();

    size_t P0 = (size_t)blockIdx.x * 128;
    {   // stage A = y * attn (bf16, padded rows)
        int row = tid >> 1, half = tid & 1;
        const uint4* src = (const uint4*)(g_yb + (P0 + row)*128 + half*64);
        char* dstrow = smem + row*272 + half*128;
        #pragma unroll
        for (int q = 0; q < 8; q++){
            uint4 raw = src[q];
            const uint32_t* rw = (const uint32_t*)&raw;
            int k0 = half*64 + q*8;
            uint32_t pk[4];
            #pragma unroll
            for (int j = 0; j < 4; j++){
                float2 f = bfunpk(rw[j]);
                f.x *= sAttn[k0 + 2*j]; f.y *= sAttn[k0 + 2*j + 1];
                pk[j] = bfpack(f.x, f.y);
            }
            *(uint4*)(dstrow + q*16) = make_uint4(pk[0], pk[1], pk[2], pk[3]);
        }
    }
    __syncthreads();

    int n0 = wid * 8;
    int br = lane & 7, bg = (lane >> 3) & 1;
    uint32_t bfr[8][2];
    #pragma unroll
    for (int kt = 0; kt < 8; kt++)
        ldsm2(bfr[kt], sb + K4A_SW_OFF + (n0 + br)*272 + bg*16 + kt*32);

    int ag = lane >> 3, ar = lane & 7;
    uint32_t abase = sb + (ar + (ag & 1)*8)*272 + (ag >> 1)*16;
    #pragma unroll 1
    for (int mt = 0; mt < 8; mt++){
        uint32_t af[8][4];
        #pragma unroll
        for (int kt = 0; kt < 8; kt++) ldsm4(af[kt], abase + mt*4352 + kt*32);
        float acc[4] = {0.f, 0.f, 0.f, 0.f};
        #pragma unroll
        for (int kt = 0; kt < 8; kt++) mma16816(acc, af[kt], bfr[kt]);
        int r0 = mt*16 + (lane >> 2);
        int c0 = n0 + (lane & 3)*2;
        float2 xv0 = *(const float2*)(x + (P0 + r0)*64 + c0);
        float2 xv1 = *(const float2*)(x + (P0 + r0 + 8)*64 + c0);
        float2 o0, o1;
        o0.x = fmaf(acc[0] + sB2[c0],   sBeta[c0],   xv0.x);
        o0.y = fmaf(acc[1] + sB2[c0+1], sBeta[c0+1], xv0.y);
        o1.x = fmaf(acc[2] + sB2[c0],   sBeta[c0],   xv1.x);
        o1.y = fmaf(acc[3] + sB2[c0+1], sBeta[c0+1], xv1.y);
        *(float2*)(g_x2 + (P0 + r0)*64 + c0)     = o0;
        *(float2*)(g_x2 + (P0 + r0 + 8)*64 + c0) = o1;
    }
}

// ---------------------------------------------------------------------------
// K4b (fused): LN2 -> pw3 -> SimpleGate (smem) -> pw4 -> out.
// ---------------------------------------------------------------------------
#define K4B_SW3_OFF  18432
#define K4B_GT_OFF   55296
#define K4B_SW4_OFF  90112
#define K4B_PAR_OFF  107520
#define K4B_SMEM     109568

__global__ void __launch_bounds__(256) k4b_fused(
    const float* __restrict__ b3v, const float* __restrict__ g2, const float* __restrict__ bb2,
    const float* __restrict__ b4v, const float* __restrict__ gamma, float* __restrict__ out)
{
    extern __shared__ char smem[];
    uint32_t sb = smem_u32(smem);
    int tid = threadIdx.x, wid = tid >> 5, lane = tid & 31;
    float* sB3 = (float*)(smem + K4B_PAR_OFF);    // 256 (interleaved)
    float* sG  = sB3 + 256;                       // 64
    float* sBe = sG + 64;                         // 64
    float* sB4 = sBe + 64;                        // 64
    float* sGa = sB4 + 64;                        // 64

    {
        const uint4* src = (const uint4*)(g_w3t + tid*64);
        uint4* dst = (uint4*)(smem + K4B_SW3_OFF + tid*144);
        #pragma unroll
        for (int q = 0; q < 8; q++) dst[q] = src[q];
    }
    {
        int row = tid >> 2, part = tid & 3;
        const uint4* src = (const uint4*)(g_w4t + row*128 + part*32);
        uint4* dst = (uint4*)(smem + K4B_SW4_OFF + row*272 + part*64);
        #pragma unroll
        for (int q = 0; q < 4; q++) dst[q] = src[q];
    }
    sB3[tid] = b3v[(tid & 1)*128 + (tid >> 1)];
    if (tid < 64){ sG[tid] = g2[tid]; sBe[tid] = bb2[tid]; }
    else if (tid < 128) sB4[tid-64] = b4v[tid-64];
    else if (tid < 192) sGa[tid-128] = gamma[tid-128];
    __syncthreads();

    size_t P0 = (size_t)blockIdx.x * 128;
    {   // LN2 of g_x2 -> A tile
        int px = tid >> 1, half = tid & 1;
        const float4* xp = (const float4*)(g_x2 + (P0 + px) * 64 + half * 32);
        float4 v[8];
        #pragma unroll
        for (int q = 0; q < 8; q++) v[q] = xp[q];
        float s = 0.f, ss = 0.f;
        #pragma unroll
        for (int q = 0; q < 8; q++){
            float4 t = v[q];
            s += t.x + t.y + t.z + t.w;
            ss = fmaf(t.x,t.x, fmaf(t.y,t.y, fmaf(t.z,t.z, fmaf(t.w,t.w, ss))));
        }
        s  += __shfl_xor_sync(0xffffffffu, s, 1);
        ss += __shfl_xor_sync(0xffffffffu, ss, 1);
        float mean = s * (1.f/64.f);
        float var  = fmaf(-mean, mean, ss * (1.f/64.f));
        float rstd = rsqrtf(var + EPSV);
        char* dstrow = smem + px*144 + half*64;
        #pragma unroll
        for (int g = 0; g < 4; g++){
            float4 va = v[2*g], vb = v[2*g+1];
            int c = half*32 + g*8;
            float f0 = fmaf((va.x-mean)*rstd, sG[c+0], sBe[c+0]);
            float f1 = fmaf((va.y-mean)*rstd, sG[c+1], sBe[c+1]);
            float f2 = fmaf((va.z-mean)*rstd, sG[c+2], sBe[c+2]);
            float f3 = fmaf((va.w-mean)*rstd, sG[c+3], sBe[c+3]);
            float f4 = fmaf((vb.x-mean)*rstd, sG[c+4], sBe[c+4]);
            float f5 = fmaf((vb.y-mean)*rstd, sG[c+5], sBe[c+5]);
            float f6 = fmaf((vb.z-mean)*rstd, sG[c+6], sBe[c+6]);
            float f7 = fmaf((vb.w-mean)*rstd, sG[c+7], sBe[c+7]);
            *(uint4*)(dstrow + g*16) = make_uint4(bfpack(f0,f1), bfpack(f2,f3),
                                                  bfpack(f4,f5), bfpack(f6,f7));
        }
    }
    __syncthreads();

    {   // phase 1: pw3 GEMM + gate -> smem
        int ns = wid * 32;
        int br = lane & 7, bg = (lane >> 3) & 1;
        uint32_t bfr[4][4][2];
        #pragma unroll
        for (int nt = 0; nt < 4; nt++)
            #pragma unroll
            for (int kt = 0; kt < 4; kt++)
                ldsm2(bfr[nt][kt], sb + K4B_SW3_OFF + (ns + nt*8 + br)*144 + bg*16 + kt*32);

        int ag = lane >> 3, ar = lane & 7;
        uint32_t abase = sb + (ar + (ag & 1)*8)*144 + (ag >> 1)*16;
        #pragma unroll 1
        for (int mt = 0; mt < 8; mt++){
            uint32_t af[4][4];
            #pragma unroll
            for (int kt = 0; kt < 4; kt++) ldsm4(af[kt], abase + mt*2304 + kt*32);
            float acc[4][4];
            #pragma unroll
            for (int nt = 0; nt < 4; nt++){ acc[nt][0]=0.f; acc[nt][1]=0.f; acc[nt][2]=0.f; acc[nt][3]=0.f; }
            #pragma unroll
            for (int kt = 0; kt < 4; kt++)
                #pragma unroll
                for (int nt = 0; nt < 4; nt++)
                    mma16816(acc[nt], af[kt], bfr[nt][kt]);
            int r0 = mt*16 + (lane >> 2);
            int c0 = ns + (lane & 3)*2;
            char* g0 = smem + K4B_GT_OFF + r0*272;
            char* g1 = g0 + 8*272;
            #pragma unroll
            for (int nt = 0; nt < 4; nt++){
                int c = c0 + nt*8;
                float ga = (acc[nt][0] + sB3[c]) * (acc[nt][1] + sB3[c+1]);
                float gb = (acc[nt][2] + sB3[c]) * (acc[nt][3] + sB3[c+1]);
                *(__nv_bfloat16*)(g0 + (c >> 1)*2) = __float2bfloat16(ga);
                *(__nv_bfloat16*)(g1 + (c >> 1)*2) = __float2bfloat16(gb);
            }
        }
    }
    __syncthreads();

    {   // phase 2: pw4 GEMM + gamma residual -> out
        int n0 = wid * 8;
        int br = lane & 7, bg = (lane >> 3) & 1;
        uint32_t bfr[8][2];
        #pragma unroll
        for (int kt = 0; kt < 8; kt++)
            ldsm2(bfr[kt], sb + K4B_SW4_OFF + (n0 + br)*272 + bg*16 + kt*32);

        int ag = lane >> 3, ar = lane & 7;
        uint32_t abase = sb + K4B_GT_OFF + (ar + (ag & 1)*8)*272 + (ag >> 1)*16;
        #pragma unroll 1
        for (int mt = 0; mt < 8; mt++){
            uint32_t af[8][4];
            #pragma unroll
            for (int kt = 0; kt < 8; kt++) ldsm4(af[kt], abase + mt*4352 + kt*32);
            float acc[4] = {0.f, 0.f, 0.f, 0.f};
            #pragma unroll
            for (int kt = 0; kt < 8; kt++) mma16816(acc, af[kt], bfr[kt]);
            int r0 = mt*16 + (lane >> 2);
            int c0 = n0 + (lane & 3)*2;
            float2 xv0 = *(const float2*)(g_x2 + (P0 + r0)*64 + c0);
            float2 xv1 = *(const float2*)(g_x2 + (P0 + r0 + 8)*64 + c0);
            float2 o0, o1;
            o0.x = fmaf(acc[0] + sB4[c0],   sGa[c0],   xv0.x);
            o0.y = fmaf(acc[1] + sB4[c0+1], sGa[c0+1], xv0.y);
            o1.x = fmaf(acc[2] + sB4[c0],   sGa[c0],   xv1.x);
            o1.y = fmaf(acc[3] + sB4[c0+1], sGa[c0+1], xv1.y);
            *(float2*)(out + (P0 + r0)*64 + c0)     = o0;
            *(float2*)(out + (P0 + r0 + 8)*64 + c0) = o1;
        }
    }
}

// ---------------------------------------------------------------------------
extern "C" void kernel_launch(void* const* d_in, const int* in_sizes, int n_in,
                              void* d_out, int out_size)
{
    const float* x    = (const float*)d_in[0];
    const float* ln1g = (const float*)d_in[1];
    const float* ln1b = (const float*)d_in[2];
    const float* pw1w = (const float*)d_in[3];
    const float* pw1b = (const float*)d_in[4];
    const float* dww  = (const float*)d_in[5];
    const float* dwb  = (const float*)d_in[6];
    const float* scaw = (const float*)d_in[7];
    const float* scab = (const float*)d_in[8];
    const float* pw2w = (const float*)d_in[9];
    const float* pw2b = (const float*)d_in[10];
    const float* beta = (const float*)d_in[11];
    const float* ln2g = (const float*)d_in[12];
    const float* ln2b = (const float*)d_in[13];
    const float* pw3w = (const float*)d_in[14];
    const float* pw3b = (const float*)d_in[15];
    const float* pw4w = (const float*)d_in[16];
    const float* pw4b = (const float*)d_in[17];
    const float* gam  = (const float*)d_in[18];
    float* out = (float*)d_out;

    cudaFuncSetAttribute(k1_ln_pw1,   cudaFuncAttributeMaxDynamicSharedMemorySize, K1_SMEM);
    cudaFuncSetAttribute(k4a_att_pw2, cudaFuncAttributeMaxDynamicSharedMemorySize, K4A_SMEM);
    cudaFuncSetAttribute(k4b_fused,   cudaFuncAttributeMaxDynamicSharedMemorySize, K4B_SMEM);

    k0_prep    <<<192, 256>>>(pw1w, pw2w, pw3w, pw4w);
    k1_ln_pw1  <<<NPIX/128, 256, K1_SMEM>>>(x, ln1g, ln1b, pw1b);
    k2_dw_gate <<<2048, 128>>>(dww, dwb);
    k3a_reduce <<<64, 128>>>();
    k3b_sca    <<<BB, 128>>>(scaw, scab);
    k4a_att_pw2<<<NPIX/128, 256, K4A_SMEM>>>(x, pw2b, beta);
    k4b_fused  <<<NPIX/128, 256, K4B_SMEM>>>(pw3b, ln2g, ln2b, pw4b, gam, out);
}

// round 13
// speedup vs baseline: 1.0213x; 1.0213x over previous
#include <cuda_runtime.h>
#include <cuda_bf16.h>
#include <cstdint>

#define EPSV 1e-6f

#define BB 8
#define HH 256
#define WW 256
#define CC 64
#define NPIX (BB*HH*WW)

// ---------------------------------------------------------------------------
// Scratch (static __device__ globals per harness rules)
// ---------------------------------------------------------------------------
__device__ __nv_bfloat16 g_t1b[(size_t)NPIX * 256];  // pw1 output (bf16)
__device__ __nv_bfloat16 g_yb [(size_t)NPIX * 128];  // gated dw out (bf16)
__device__ float g_part[BB * 1024 * 128];            // GAP partials
__device__ float g_part2[128 * 128];                 // GAP stage-2 partials
__device__ float g_attn[BB * 128];                   // channel attention
// Transposed bf16 weights (n-major rows, k contiguous)
__device__ __align__(16) __nv_bfloat16 g_w1t[256*64];
__device__ __align__(16) __nv_bfloat16 g_w2t[64*128];
__device__ __align__(16) __nv_bfloat16 g_w3t[256*64];   // gate-interleaved rows
__device__ __align__(16) __nv_bfloat16 g_w4t[64*128];

// ---------------------------------------------------------------------------
// Helpers
// ---------------------------------------------------------------------------
__device__ __forceinline__ uint32_t smem_u32(const void* p){
    uint32_t a; asm("{ .reg .u64 t; cvta.to.shared.u64 t, %1; cvt.u32.u64 %0, t; }" : "=r"(a) : "l"(p)); return a;
}
__device__ __forceinline__ void ldsm4(uint32_t* r, uint32_t addr){
    asm volatile("ldmatrix.sync.aligned.m8n8.x4.shared.b16 {%0,%1,%2,%3}, [%4];"
        : "=r"(r[0]), "=r"(r[1]), "=r"(r[2]), "=r"(r[3]) : "r"(addr));
}
__device__ __forceinline__ void ldsm2(uint32_t* r, uint32_t addr){
    asm volatile("ldmatrix.sync.aligned.m8n8.x2.shared.b16 {%0,%1}, [%2];"
        : "=r"(r[0]), "=r"(r[1]) : "r"(addr));
}
__device__ __forceinline__ void mma16816(float* d, const uint32_t* a, const uint32_t* b){
    asm volatile("mma.sync.aligned.m16n8k16.row.col.f32.bf16.bf16.f32 "
        "{%0,%1,%2,%3}, {%4,%5,%6,%7}, {%8,%9}, {%0,%1,%2,%3};"
        : "+f"(d[0]), "+f"(d[1]), "+f"(d[2]), "+f"(d[3])
        : "r"(a[0]), "r"(a[1]), "r"(a[2]), "r"(a[3]), "r"(b[0]), "r"(b[1]));
}
__device__ __forceinline__ uint32_t bfpack(float a, float b){
    __nv_bfloat162 h = __floats2bfloat162_rn(a, b);
    return *(uint32_t*)&h;
}
__device__ __forceinline__ float2 bfunpk(uint32_t u){
    __nv_bfloat162 h = *(__nv_bfloat162*)&u;
    return __bfloat1622float2(h);
}
__device__ __forceinline__ void st_bf2(__nv_bfloat16* p, float a, float b){
    *(__nv_bfloat162*)p = __floats2bfloat162_rn(a, b);
}

// ---------------------------------------------------------------------------
// K0: weight prep — transposed bf16 (n-major)
// ---------------------------------------------------------------------------
__global__ void k0_prep(const float* __restrict__ w1, const float* __restrict__ w2,
                        const float* __restrict__ w3, const float* __restrict__ w4)
{
    int idx = blockIdx.x * 256 + threadIdx.x;     // 192*256 = 49152
    if (idx < 16384){                             // w1t [256 n][64 k]
        int n = idx >> 6, k = idx & 63;
        g_w1t[n*64 + k] = __float2bfloat16(w1[k*256 + n]);
    } else if (idx < 24576){                      // w2t [64 n][128 k]
        int i = idx - 16384; int n = i >> 7, k = i & 127;
        g_w2t[n*128 + k] = __float2bfloat16(w2[k*64 + n]);
    } else if (idx < 40960){                      // w3t interleaved [256 n][64 k]
        int i = idx - 24576; int n = i >> 6, k = i & 63;
        g_w3t[n*64 + k] = __float2bfloat16(w3[k*256 + (n & 1)*128 + (n >> 1)]);
    } else {                                      // w4t [64 n][128 k]
        int i = idx - 40960; int n = i >> 7, k = i & 127;
        g_w4t[n*128 + k] = __float2bfloat16(w4[k*64 + n]);
    }
}

// ---------------------------------------------------------------------------
// K1: LN1 + pw1 (64 -> 256) via mma.sync. 128 px/block, 256 threads (8 warps).
// (R11 version — direct epilogue stores)
// ---------------------------------------------------------------------------
#define K1_SW_OFF   18432
#define K1_PAR_OFF  55296
#define K1_SMEM     56832

__global__ void __launch_bounds__(256) k1_ln_pw1(
    const float* __restrict__ x, const float* __restrict__ g1,
    const float* __restrict__ b1v, const float* __restrict__ bias)
{
    extern __shared__ char smem[];
    uint32_t sb = smem_u32(smem);
    int tid = threadIdx.x, wid = tid >> 5, lane = tid & 31;
    float* sBias = (float*)(smem + K1_PAR_OFF);   // 256
    float* sG  = sBias + 256;                     // 64
    float* sBe = sG + 64;                         // 64

    {
        const uint4* src = (const uint4*)(g_w1t + tid*64);
        uint4* dst = (uint4*)(smem + K1_SW_OFF + tid*144);
        #pragma unroll
        for (int q = 0; q < 8; q++) dst[q] = src[q];
    }
    sBias[tid] = bias[tid];
    if (tid < 64){ sG[tid] = g1[tid]; sBe[tid] = b1v[tid]; }
    __syncthreads();

    size_t P0 = (size_t)blockIdx.x * 128;
    {   // LN: 2 threads per pixel
        int px = tid >> 1, half = tid & 1;
        const float4* xp = (const float4*)(x + (P0 + px) * 64 + half * 32);
        float4 v[8];
        #pragma unroll
        for (int q = 0; q < 8; q++) v[q] = xp[q];
        float s = 0.f, ss = 0.f;
        #pragma unroll
        for (int q = 0; q < 8; q++){
            float4 t = v[q];
            s += t.x + t.y + t.z + t.w;
            ss = fmaf(t.x,t.x, fmaf(t.y,t.y, fmaf(t.z,t.z, fmaf(t.w,t.w, ss))));
        }
        s  += __shfl_xor_sync(0xffffffffu, s, 1);
        ss += __shfl_xor_sync(0xffffffffu, ss, 1);
        float mean = s * (1.f/64.f);
        float var  = fmaf(-mean, mean, ss * (1.f/64.f));
        float rstd = rsqrtf(var + EPSV);
        char* dstrow = smem + px*144 + half*64;
        #pragma unroll
        for (int g = 0; g < 4; g++){
            float4 va = v[2*g], vb = v[2*g+1];
            int c = half*32 + g*8;
            float f0 = fmaf((va.x-mean)*rstd, sG[c+0], sBe[c+0]);
            float f1 = fmaf((va.y-mean)*rstd, sG[c+1], sBe[c+1]);
            float f2 = fmaf((va.z-mean)*rstd, sG[c+2], sBe[c+2]);
            float f3 = fmaf((va.w-mean)*rstd, sG[c+3], sBe[c+3]);
            float f4 = fmaf((vb.x-mean)*rstd, sG[c+4], sBe[c+4]);
            float f5 = fmaf((vb.y-mean)*rstd, sG[c+5], sBe[c+5]);
            float f6 = fmaf((vb.z-mean)*rstd, sG[c+6], sBe[c+6]);
            float f7 = fmaf((vb.w-mean)*rstd, sG[c+7], sBe[c+7]);
            *(uint4*)(dstrow + g*16) = make_uint4(bfpack(f0,f1), bfpack(f2,f3),
                                                  bfpack(f4,f5), bfpack(f6,f7));
        }
    }
    __syncthreads();

    int ns = wid * 32;
    int br = lane & 7, bg = (lane >> 3) & 1;
    uint32_t bfr[4][4][2];
    #pragma unroll
    for (int nt = 0; nt < 4; nt++)
        #pragma unroll
        for (int kt = 0; kt < 4; kt++)
            ldsm2(bfr[nt][kt], sb + K1_SW_OFF + (ns + nt*8 + br)*144 + bg*16 + kt*32);

    int ag = lane >> 3, ar = lane & 7;
    uint32_t abase = sb + (ar + (ag & 1)*8)*144 + (ag >> 1)*16;
    #pragma unroll 1
    for (int mt = 0; mt < 8; mt++){
        uint32_t af[4][4];
        #pragma unroll
        for (int kt = 0; kt < 4; kt++) ldsm4(af[kt], abase + mt*2304 + kt*32);
        float acc[4][4];
        #pragma unroll
        for (int nt = 0; nt < 4; nt++){ acc[nt][0]=0.f; acc[nt][1]=0.f; acc[nt][2]=0.f; acc[nt][3]=0.f; }
        #pragma unroll
        for (int kt = 0; kt < 4; kt++)
            #pragma unroll
            for (int nt = 0; nt < 4; nt++)
                mma16816(acc[nt], af[kt], bfr[nt][kt]);
        int r0 = mt*16 + (lane >> 2);
        int c0 = ns + (lane & 3)*2;
        __nv_bfloat16* o0 = g_t1b + (P0 + r0)*256;
        __nv_bfloat16* o1 = o0 + 8*256;
        #pragma unroll
        for (int nt = 0; nt < 4; nt++){
            int c = c0 + nt*8;
            st_bf2(o0 + c, acc[nt][0] + sBias[c], acc[nt][1] + sBias[c+1]);
            st_bf2(o1 + c, acc[nt][2] + sBias[c], acc[nt][3] + sBias[c+1]);
        }
    }
}

// ---------------------------------------------------------------------------
// K2: depthwise 3x3 + SimpleGate + GAP partials (bf16 I/O) — R11 version
// ---------------------------------------------------------------------------
__global__ void __launch_bounds__(128) k2_dw_gate(const float* __restrict__ dww, const float* __restrict__ dwb)
{
    int blk = blockIdx.x;            // b*512 + h*2 + wseg
    int b   = blk >> 9;
    int rem = blk & 511;
    int h   = rem >> 1;
    int wseg= rem & 1;
    int sub = threadIdx.x >> 6;
    int c2  = threadIdx.x & 63;
    int ch  = c2 * 2;
    int w0  = wseg*128 + sub*64;

    float2 wt0[9], wt1[9];
    #pragma unroll
    for (int i = 0; i < 9; i++){
        wt0[i] = make_float2(dww[i*256 + ch],       dww[i*256 + ch + 1]);
        wt1[i] = make_float2(dww[i*256 + 128 + ch], dww[i*256 + 128 + ch + 1]);
    }
    float2 bc0 = make_float2(dwb[ch], dwb[ch+1]);
    float2 bc1 = make_float2(dwb[128+ch], dwb[128+ch+1]);

    const __nv_bfloat162* img = (const __nv_bfloat162*)g_t1b;
    size_t rowb = (size_t)(b*256 + h) * 256;
    bool v0 = (h > 0), v2 = (h < HH-1);
    #define LD0(rr, wc) __bfloat1622float2(img[((rr) + (size_t)(wc))*128 + c2])
    #define LD1(rr, wc) __bfloat1622float2(img[((rr) + (size_t)(wc))*128 + 64 + c2])
    size_t r0 = rowb - 256, r1 = rowb, r2 = rowb + 256;
    const float2 Z = make_float2(0.f, 0.f);

    float2 win0[9], win1[9];
    {
        int wm = w0 - 1; bool vm = (wm >= 0);
        win0[0] = (v0 && vm) ? LD0(r0, wm) : Z;
        win0[3] =  vm        ? LD0(r1, wm) : Z;
        win0[6] = (v2 && vm) ? LD0(r2, wm) : Z;
        win1[0] = (v0 && vm) ? LD1(r0, wm) : Z;
        win1[3] =  vm        ? LD1(r1, wm) : Z;
        win1[6] = (v2 && vm) ? LD1(r2, wm) : Z;
        win0[1] = v0 ? LD0(r0, w0) : Z;
        win0[4] =      LD0(r1, w0);
        win0[7] = v2 ? LD0(r2, w0) : Z;
        win1[1] = v0 ? LD1(r0, w0) : Z;
        win1[4] =      LD1(r1, w0);
        win1[7] = v2 ? LD1(r2, w0) : Z;
    }
    __nv_bfloat162* yrow = (__nv_bfloat162*)g_yb;
    float2 gap = Z;
    for (int w = w0; w < w0 + 64; w++){
        int wp = w + 1; bool vp = (wp < WW);
        win0[2] = (v0 && vp) ? LD0(r0, wp) : Z;
        win0[5] =  vp        ? LD0(r1, wp) : Z;
        win0[8] = (v2 && vp) ? LD0(r2, wp) : Z;
        win1[2] = (v0 && vp) ? LD1(r0, wp) : Z;
        win1[5] =  vp        ? LD1(r1, wp) : Z;
        win1[8] = (v2 && vp) ? LD1(r2, wp) : Z;
        float2 a = bc0, c = bc1;
        #pragma unroll
        for (int i = 0; i < 9; i++){
            a.x = fmaf(win0[i].x, wt0[i].x, a.x); a.y = fmaf(win0[i].y, wt0[i].y, a.y);
            c.x = fmaf(win1[i].x, wt1[i].x, c.x); c.y = fmaf(win1[i].y, wt1[i].y, c.y);
        }
        float2 yv = make_float2(a.x * c.x, a.y * c.y);
        yrow[(rowb + (size_t)w)*64 + c2] = __floats2bfloat162_rn(yv.x, yv.y);
        gap.x += yv.x; gap.y += yv.y;
        #pragma unroll
        for (int r = 0; r < 3; r++){
            win0[r*3+0] = win0[r*3+1]; win0[r*3+1] = win0[r*3+2];
            win1[r*3+0] = win1[r*3+1]; win1[r*3+1] = win1[r*3+2];
        }
    }
    int pid = blk*2 + sub;
    g_part[(size_t)pid*128 + ch]     = gap.x;
    g_part[(size_t)pid*128 + ch + 1] = gap.y;
    #undef LD0
    #undef LD1
}

// ---------------------------------------------------------------------------
// K3a: GAP partial reduce (128 blocks x 128 threads, 64 rows each)
// ---------------------------------------------------------------------------
__global__ void __launch_bounds__(128) k3a_reduce()
{
    int blk = blockIdx.x;
    int c = threadIdx.x;
    const float* p = g_part + (size_t)blk * 64 * 128 + c;
    float s = 0.f;
    #pragma unroll 16
    for (int i = 0; i < 64; i++) s += p[(size_t)i * 128];
    g_part2[blk*128 + c] = s;
}

// ---------------------------------------------------------------------------
// K3b: final GAP reduce + SCA
// ---------------------------------------------------------------------------
__global__ void k3b_sca(const float* __restrict__ scaw, const float* __restrict__ scab)
{
    __shared__ float smn[128];
    int b = blockIdx.x, c = threadIdx.x;
    float s = 0.f;
    #pragma unroll
    for (int i = 0; i < 16; i++) s += g_part2[(b*16 + i)*128 + c];
    smn[c] = s * (1.f / 65536.f);
    __syncthreads();
    float a = scab[c];
    #pragma unroll 8
    for (int k = 0; k < 128; k++) a = fmaf(smn[k], scaw[k*128 + c], a);
    g_attn[b*128 + c] = a;
}

// ---------------------------------------------------------------------------
// K4 (fully fused stage-1-epilogue + stage-2):
//   stage A=y*attn -> pw2 GEMM -> x2 (smem fp32) -> LN2 -> pw3 GEMM -> gate
//   (smem) -> pw4 GEMM -> out = x2 + .*gamma
// smem regions (272B / 144B padded rows):
//   AY  [0,      34816): y*attn bf16 (ph1-2) -> gate bf16 (ph4-5), 272B rows
//   W   [34816,  71680): w2 (272B x64) -> w3 (144B x256) -> w4 (272B x64)
//   ALN [71680,  90112): LN2 out bf16, 144B x128
//   X2  [90112, 124928): x2 fp32, 272B rows (68 words)
//   PAR [124928,128000): params
// 128000 B -> 1 block/SM
// ---------------------------------------------------------------------------
#define K4_AY_OFF   0
#define K4_W_OFF    34816
#define K4_ALN_OFF  71680
#define K4_X2_OFF   90112
#define K4_PAR_OFF  124928
#define K4_SMEM     128000

__global__ void __launch_bounds__(256) k4_fused(
    const float* __restrict__ x,
    const float* __restrict__ b2v, const float* __restrict__ beta,
    const float* __restrict__ b3v, const float* __restrict__ g2, const float* __restrict__ bb2,
    const float* __restrict__ b4v, const float* __restrict__ gamma, float* __restrict__ out)
{
    extern __shared__ char smem[];
    uint32_t sb = smem_u32(smem);
    int tid = threadIdx.x, wid = tid >> 5, lane = tid & 31;
    float* sAttn = (float*)(smem + K4_PAR_OFF);   // 128
    float* sB2   = sAttn + 128;                   // 64
    float* sBeta = sB2 + 64;                      // 64
    float* sB3   = sBeta + 64;                    // 256 (interleaved)
    float* sG    = sB3 + 256;                     // 64
    float* sBe   = sG + 64;                       // 64
    float* sB4   = sBe + 64;                      // 64
    float* sGa   = sB4 + 64;                      // 64
    float* x2s   = (float*)(smem + K4_X2_OFF);    // [128 rows x 68 words]
    int b = blockIdx.x >> 9;

    // ---- ph0: params + w2 ----
    {
        int row = tid >> 2, part = tid & 3;
        const uint4* src = (const uint4*)(g_w2t + row*128 + part*32);
        uint4* dst = (uint4*)(smem + K4_W_OFF + row*272 + part*64);
        #pragma unroll
        for (int q = 0; q < 4; q++) dst[q] = src[q];
    }
    sB3[tid] = b3v[(tid & 1)*128 + (tid >> 1)];
    if (tid < 128) sAttn[tid] = g_attn[b*128 + tid];
    else if (tid < 192) sB2[tid-128] = b2v[tid-128];
    else sBeta[tid-192] = beta[tid-192];
    if (tid < 64) sG[tid] = g2[tid];
    else if (tid < 128) sBe[tid-64] = bb2[tid-64];
    else if (tid < 192) sB4[tid-128] = b4v[tid-128];
    else sGa[tid-192] = gamma[tid-192];
    __syncthreads();

    size_t P0 = (size_t)blockIdx.x * 128;
    // ---- ph1: stage A = y * attn (bf16, 272B rows at AY) ----
    {
        int row = tid >> 1, half = tid & 1;
        const uint4* src = (const uint4*)(g_yb + (P0 + row)*128 + half*64);
        char* dstrow = smem + K4_AY_OFF + row*272 + half*128;
        #pragma unroll
        for (int q = 0; q < 8; q++){
            uint4 raw = src[q];
            const uint32_t* rw = (const uint32_t*)&raw;
            int k0 = half*64 + q*8;
            uint32_t pk[4];
            #pragma unroll
            for (int j = 0; j < 4; j++){
                float2 f = bfunpk(rw[j]);
                f.x *= sAttn[k0 + 2*j]; f.y *= sAttn[k0 + 2*j + 1];
                pk[j] = bfpack(f.x, f.y);
            }
            *(uint4*)(dstrow + q*16) = make_uint4(pk[0], pk[1], pk[2], pk[3]);
        }
    }
    __syncthreads();

    // ---- ph2: pw2 GEMM (n-slice 8/warp) -> x2 = x + (.)*beta -> smem ----
    {
        int n0 = wid * 8;
        int br = lane & 7, bg = (lane >> 3) & 1;
        uint32_t bfr[8][2];
        #pragma unroll
        for (int kt = 0; kt < 8; kt++)
            ldsm2(bfr[kt], sb + K4_W_OFF + (n0 + br)*272 + bg*16 + kt*32);

        int ag = lane >> 3, ar = lane & 7;
        uint32_t abase = sb + K4_AY_OFF + (ar + (ag & 1)*8)*272 + (ag >> 1)*16;
        #pragma unroll 1
        for (int mt = 0; mt < 8; mt++){
            uint32_t af[8][4];
            #pragma unroll
            for (int kt = 0; kt < 8; kt++) ldsm4(af[kt], abase + mt*4352 + kt*32);
            float acc[4] = {0.f, 0.f, 0.f, 0.f};
            #pragma unroll
            for (int kt = 0; kt < 8; kt++) mma16816(acc, af[kt], bfr[kt]);
            int r0 = mt*16 + (lane >> 2);
            int c0 = n0 + (lane & 3)*2;
            float2 xv0 = *(const float2*)(x + (P0 + r0)*64 + c0);
            float2 xv1 = *(const float2*)(x + (P0 + r0 + 8)*64 + c0);
            float2 o0, o1;
            o0.x = fmaf(acc[0] + sB2[c0],   sBeta[c0],   xv0.x);
            o0.y = fmaf(acc[1] + sB2[c0+1], sBeta[c0+1], xv0.y);
            o1.x = fmaf(acc[2] + sB2[c0],   sBeta[c0],   xv1.x);
            o1.y = fmaf(acc[3] + sB2[c0+1], sBeta[c0+1], xv1.y);
            *(float2*)(x2s + r0*68 + c0)       = o0;
            *(float2*)(x2s + (r0 + 8)*68 + c0) = o1;
        }
    }
    __syncthreads();

    // ---- ph3: load w3 (overwrites w2) + LN2 from x2 smem -> ALN ----
    {
        const uint4* src = (const uint4*)(g_w3t + tid*64);
        uint4* dst = (uint4*)(smem + K4_W_OFF + tid*144);
        #pragma unroll
        for (int q = 0; q < 8; q++) dst[q] = src[q];
    }
    {
        int px = tid >> 1, half = tid & 1;
        const float* xr = x2s + px*68 + half*32;
        float4 v[8];
        #pragma unroll
        for (int q = 0; q < 8; q++) v[q] = *(const float4*)(xr + 4*q);
        float s = 0.f, ss = 0.f;
        #pragma unroll
        for (int q = 0; q < 8; q++){
            float4 t = v[q];
            s += t.x + t.y + t.z + t.w;
            ss = fmaf(t.x,t.x, fmaf(t.y,t.y, fmaf(t.z,t.z, fmaf(t.w,t.w, ss))));
        }
        s  += __shfl_xor_sync(0xffffffffu, s, 1);
        ss += __shfl_xor_sync(0xffffffffu, ss, 1);
        float mean = s * (1.f/64.f);
        float var  = fmaf(-mean, mean, ss * (1.f/64.f));
        float rstd = rsqrtf(var + EPSV);
        char* dstrow = smem + K4_ALN_OFF + px*144 + half*64;
        #pragma unroll
        for (int g = 0; g < 4; g++){
            float4 va = v[2*g], vb = v[2*g+1];
            int c = half*32 + g*8;
            float f0 = fmaf((va.x-mean)*rstd, sG[c+0], sBe[c+0]);
            float f1 = fmaf((va.y-mean)*rstd, sG[c+1], sBe[c+1]);
            float f2 = fmaf((va.z-mean)*rstd, sG[c+2], sBe[c+2]);
            float f3 = fmaf((va.w-mean)*rstd, sG[c+3], sBe[c+3]);
            float f4 = fmaf((vb.x-mean)*rstd, sG[c+4], sBe[c+4]);
            float f5 = fmaf((vb.y-mean)*rstd, sG[c+5], sBe[c+5]);
            float f6 = fmaf((vb.z-mean)*rstd, sG[c+6], sBe[c+6]);
            float f7 = fmaf((vb.w-mean)*rstd, sG[c+7], sBe[c+7]);
            *(uint4*)(dstrow + g*16) = make_uint4(bfpack(f0,f1), bfpack(f2,f3),
                                                  bfpack(f4,f5), bfpack(f6,f7));
        }
    }
    __syncthreads();

    // ---- ph4: pw3 GEMM (n-slice 32, interleaved) + gate -> AY region ----
    {
        int ns = wid * 32;
        int br = lane & 7, bg = (lane >> 3) & 1;
        uint32_t bfr[4][4][2];
        #pragma unroll
        for (int nt = 0; nt < 4; nt++)
            #pragma unroll
            for (int kt = 0; kt < 4; kt++)
                ldsm2(bfr[nt][kt], sb + K4_W_OFF + (ns + nt*8 + br)*144 + bg*16 + kt*32);

        int ag = lane >> 3, ar = lane & 7;
        uint32_t abase = sb + K4_ALN_OFF + (ar + (ag & 1)*8)*144 + (ag >> 1)*16;
        #pragma unroll 1
        for (int mt = 0; mt < 8; mt++){
            uint32_t af[4][4];
            #pragma unroll
            for (int kt = 0; kt < 4; kt++) ldsm4(af[kt], abase + mt*2304 + kt*32);
            float acc[4][4];
            #pragma unroll
            for (int nt = 0; nt < 4; nt++){ acc[nt][0]=0.f; acc[nt][1]=0.f; acc[nt][2]=0.f; acc[nt][3]=0.f; }
            #pragma unroll
            for (int kt = 0; kt < 4; kt++)
                #pragma unroll
                for (int nt = 0; nt < 4; nt++)
                    mma16816(acc[nt], af[kt], bfr[nt][kt]);
            int r0 = mt*16 + (lane >> 2);
            int c0 = ns + (lane & 3)*2;
            char* g0 = smem + K4_AY_OFF + r0*272;
            char* g1 = g0 + 8*272;
            #pragma unroll
            for (int nt = 0; nt < 4; nt++){
                int c = c0 + nt*8;
                float ga = (acc[nt][0] + sB3[c]) * (acc[nt][1] + sB3[c+1]);
                float gb = (acc[nt][2] + sB3[c]) * (acc[nt][3] + sB3[c+1]);
                *(__nv_bfloat16*)(g0 + (c >> 1)*2) = __float2bfloat16(ga);
                *(__nv_bfloat16*)(g1 + (c >> 1)*2) = __float2bfloat16(gb);
            }
        }
    }
    __syncthreads();

    // ---- ph5: load w4 (overwrites w3) ----
    {
        int row = tid >> 2, part = tid & 3;
        const uint4* src = (const uint4*)(g_w4t + row*128 + part*32);
        uint4* dst = (uint4*)(smem + K4_W_OFF + row*272 + part*64);
        #pragma unroll
        for (int q = 0; q < 4; q++) dst[q] = src[q];
    }
    __syncthreads();

    // ---- ph6: pw4 GEMM (n-slice 8) + gamma residual from x2 smem -> out ----
    {
        int n0 = wid * 8;
        int br = lane & 7, bg = (lane >> 3) & 1;
        uint32_t bfr[8][2];
        #pragma unroll
        for (int kt = 0; kt < 8; kt++)
            ldsm2(bfr[kt], sb + K4_W_OFF + (n0 + br)*272 + bg*16 + kt*32);

        int ag = lane >> 3, ar = lane & 7;
        uint32_t abase = sb + K4_AY_OFF + (ar + (ag & 1)*8)*272 + (ag >> 1)*16;
        #pragma unroll 1
        for (int mt = 0; mt < 8; mt++){
            uint32_t af[8][4];
            #pragma unroll
            for (int kt = 0; kt < 8; kt++) ldsm4(af[kt], abase + mt*4352 + kt*32);
            float acc[4] = {0.f, 0.f, 0.f, 0.f};
            #pragma unroll
            for (int kt = 0; kt < 8; kt++) mma16816(acc, af[kt], bfr[kt]);
            int r0 = mt*16 + (lane >> 2);
            int c0 = n0 + (lane & 3)*2;
            float2 xv0 = *(const float2*)(x2s + r0*68 + c0);
            float2 xv1 = *(const float2*)(x2s + (r0 + 8)*68 + c0);
            float2 o0, o1;
            o0.x = fmaf(acc[0] + sB4[c0],   sGa[c0],   xv0.x);
            o0.y = fmaf(acc[1] + sB4[c0+1], sGa[c0+1], xv0.y);
            o1.x = fmaf(acc[2] + sB4[c0],   sGa[c0],   xv1.x);
            o1.y = fmaf(acc[3] + sB4[c0+1], sGa[c0+1], xv1.y);
            *(float2*)(out + (P0 + r0)*64 + c0)     = o0;
            *(float2*)(out + (P0 + r0 + 8)*64 + c0) = o1;
        }
    }
}

// ---------------------------------------------------------------------------
extern "C" void kernel_launch(void* const* d_in, const int* in_sizes, int n_in,
                              void* d_out, int out_size)
{
    const float* x    = (const float*)d_in[0];
    const float* ln1g = (const float*)d_in[1];
    const float* ln1b = (const float*)d_in[2];
    const float* pw1w = (const float*)d_in[3];
    const float* pw1b = (const float*)d_in[4];
    const float* dww  = (const float*)d_in[5];
    const float* dwb  = (const float*)d_in[6];
    const float* scaw = (const float*)d_in[7];
    const float* scab = (const float*)d_in[8];
    const float* pw2w = (const float*)d_in[9];
    const float* pw2b = (const float*)d_in[10];
    const float* beta = (const float*)d_in[11];
    const float* ln2g = (const float*)d_in[12];
    const float* ln2b = (const float*)d_in[13];
    const float* pw3w = (const float*)d_in[14];
    const float* pw3b = (const float*)d_in[15];
    const float* pw4w = (const float*)d_in[16];
    const float* pw4b = (const float*)d_in[17];
    const float* gam  = (const float*)d_in[18];
    float* out = (float*)d_out;

    cudaFuncSetAttribute(k1_ln_pw1, cudaFuncAttributeMaxDynamicSharedMemorySize, K1_SMEM);
    cudaFuncSetAttribute(k4_fused,  cudaFuncAttributeMaxDynamicSharedMemorySize, K4_SMEM);

    k0_prep    <<<192, 256>>>(pw1w, pw2w, pw3w, pw4w);
    k1_ln_pw1  <<<NPIX/128, 256, K1_SMEM>>>(x, ln1g, ln1b, pw1b);
    k2_dw_gate <<<BB*512, 128>>>(dww, dwb);
    k3a_reduce <<<128, 128>>>();
    k3b_sca    <<<BB, 128>>>(scaw, scab);
    k4_fused   <<<NPIX/128, 256, K4_SMEM>>>(x, pw2b, beta, pw3b, ln2g, ln2b, pw4b, gam, out);
}

// round 14
// speedup vs baseline: 1.0717x; 1.0494x over previous
#include <cuda_runtime.h>
#include <cuda_bf16.h>
#include <cstdint>

#define EPSV 1e-6f

#define BB 8
#define HH 256
#define WW 256
#define CC 64
#define NPIX (BB*HH*WW)

// ---------------------------------------------------------------------------
// Scratch (static __device__ globals per harness rules)
// ---------------------------------------------------------------------------
__device__ __nv_bfloat16 g_t1b[(size_t)NPIX * 256];  // pw1 output (bf16)
__device__ __nv_bfloat16 g_yb [(size_t)NPIX * 128];  // gated dw out (bf16)
__device__ float g_x2[(size_t)NPIX * CC];            // stage-1 residual (fp32)
__device__ float g_part[8192 * 128];                 // GAP partials
__device__ float g_part2[128 * 128];                 // GAP stage-2 partials
__device__ float g_attn[BB * 128];                   // channel attention
// Transposed bf16 weights (n-major rows, k contiguous)
__device__ __align__(16) __nv_bfloat16 g_w1t[256*64];
__device__ __align__(16) __nv_bfloat16 g_w2t[64*128];
__device__ __align__(16) __nv_bfloat16 g_w3t[256*64];   // gate-interleaved rows
__device__ __align__(16) __nv_bfloat16 g_w4t[64*128];

// ---------------------------------------------------------------------------
// Helpers
// ---------------------------------------------------------------------------
__device__ __forceinline__ uint32_t smem_u32(const void* p){
    uint32_t a; asm("{ .reg .u64 t; cvta.to.shared.u64 t, %1; cvt.u32.u64 %0, t; }" : "=r"(a) : "l"(p)); return a;
}
__device__ __forceinline__ void ldsm4(uint32_t* r, uint32_t addr){
    asm volatile("ldmatrix.sync.aligned.m8n8.x4.shared.b16 {%0,%1,%2,%3}, [%4];"
        : "=r"(r[0]), "=r"(r[1]), "=r"(r[2]), "=r"(r[3]) : "r"(addr));
}
__device__ __forceinline__ void ldsm2(uint32_t* r, uint32_t addr){
    asm volatile("ldmatrix.sync.aligned.m8n8.x2.shared.b16 {%0,%1}, [%2];"
        : "=r"(r[0]), "=r"(r[1]) : "r"(addr));
}
__device__ __forceinline__ void mma16816(float* d, const uint32_t* a, const uint32_t* b){
    asm volatile("mma.sync.aligned.m16n8k16.row.col.f32.bf16.bf16.f32 "
        "{%0,%1,%2,%3}, {%4,%5,%6,%7}, {%8,%9}, {%0,%1,%2,%3};"
        : "+f"(d[0]), "+f"(d[1]), "+f"(d[2]), "+f"(d[3])
        : "r"(a[0]), "r"(a[1]), "r"(a[2]), "r"(a[3]), "r"(b[0]), "r"(b[1]));
}
__device__ __forceinline__ uint32_t bfpack(float a, float b){
    __nv_bfloat162 h = __floats2bfloat162_rn(a, b);
    return *(uint32_t*)&h;
}
__device__ __forceinline__ float2 bfunpk(uint32_t u){
    __nv_bfloat162 h = *(__nv_bfloat162*)&u;
    return __bfloat1622float2(h);
}
__device__ __forceinline__ void st_bf2(__nv_bfloat16* p, float a, float b){
    *(__nv_bfloat162*)p = __floats2bfloat162_rn(a, b);
}
__device__ __forceinline__ float4 bf4(uint2 u){
    float2 a = bfunpk(u.x), b = bfunpk(u.y);
    return make_float4(a.x, a.y, b.x, b.y);
}

// ---------------------------------------------------------------------------
// K0: weight prep — transposed bf16 (n-major)
// ---------------------------------------------------------------------------
__global__ void k0_prep(const float* __restrict__ w1, const float* __restrict__ w2,
                        const float* __restrict__ w3, const float* __restrict__ w4)
{
    int idx = blockIdx.x * 256 + threadIdx.x;     // 192*256 = 49152
    if (idx < 16384){                             // w1t [256 n][64 k]
        int n = idx >> 6, k = idx & 63;
        g_w1t[n*64 + k] = __float2bfloat16(w1[k*256 + n]);
    } else if (idx < 24576){                      // w2t [64 n][128 k]
        int i = idx - 16384; int n = i >> 7, k = i & 127;
        g_w2t[n*128 + k] = __float2bfloat16(w2[k*64 + n]);
    } else if (idx < 40960){                      // w3t interleaved [256 n][64 k]
        int i = idx - 24576; int n = i >> 6, k = i & 63;
        g_w3t[n*64 + k] = __float2bfloat16(w3[k*256 + (n & 1)*128 + (n >> 1)]);
    } else {                                      // w4t [64 n][128 k]
        int i = idx - 40960; int n = i >> 7, k = i & 127;
        g_w4t[n*128 + k] = __float2bfloat16(w4[k*64 + n]);
    }
}

// ---------------------------------------------------------------------------
// K1: LN1 + pw1 (64 -> 256) via mma.sync. 128 px/block, 256 threads (8 warps).
// (R11 version — direct epilogue stores)
// ---------------------------------------------------------------------------
#define K1_SW_OFF   18432
#define K1_PAR_OFF  55296
#define K1_SMEM     56832

__global__ void __launch_bounds__(256) k1_ln_pw1(
    const float* __restrict__ x, const float* __restrict__ g1,
    const float* __restrict__ b1v, const float* __restrict__ bias)
{
    extern __shared__ char smem[];
    uint32_t sb = smem_u32(smem);
    int tid = threadIdx.x, wid = tid >> 5, lane = tid & 31;
    float* sBias = (float*)(smem + K1_PAR_OFF);   // 256
    float* sG  = sBias + 256;                     // 64
    float* sBe = sG + 64;                         // 64

    {
        const uint4* src = (const uint4*)(g_w1t + tid*64);
        uint4* dst = (uint4*)(smem + K1_SW_OFF + tid*144);
        #pragma unroll
        for (int q = 0; q < 8; q++) dst[q] = src[q];
    }
    sBias[tid] = bias[tid];
    if (tid < 64){ sG[tid] = g1[tid]; sBe[tid] = b1v[tid]; }
    __syncthreads();

    size_t P0 = (size_t)blockIdx.x * 128;
    {   // LN: 2 threads per pixel
        int px = tid >> 1, half = tid & 1;
        const float4* xp = (const float4*)(x + (P0 + px) * 64 + half * 32);
        float4 v[8];
        #pragma unroll
        for (int q = 0; q < 8; q++) v[q] = xp[q];
        float s = 0.f, ss = 0.f;
        #pragma unroll
        for (int q = 0; q < 8; q++){
            float4 t = v[q];
            s += t.x + t.y + t.z + t.w;
            ss = fmaf(t.x,t.x, fmaf(t.y,t.y, fmaf(t.z,t.z, fmaf(t.w,t.w, ss))));
        }
        s  += __shfl_xor_sync(0xffffffffu, s, 1);
        ss += __shfl_xor_sync(0xffffffffu, ss, 1);
        float mean = s * (1.f/64.f);
        float var  = fmaf(-mean, mean, ss * (1.f/64.f));
        float rstd = rsqrtf(var + EPSV);
        char* dstrow = smem + px*144 + half*64;
        #pragma unroll
        for (int g = 0; g < 4; g++){
            float4 va = v[2*g], vb = v[2*g+1];
            int c = half*32 + g*8;
            float f0 = fmaf((va.x-mean)*rstd, sG[c+0], sBe[c+0]);
            float f1 = fmaf((va.y-mean)*rstd, sG[c+1], sBe[c+1]);
            float f2 = fmaf((va.z-mean)*rstd, sG[c+2], sBe[c+2]);
            float f3 = fmaf((va.w-mean)*rstd, sG[c+3], sBe[c+3]);
            float f4 = fmaf((vb.x-mean)*rstd, sG[c+4], sBe[c+4]);
            float f5 = fmaf((vb.y-mean)*rstd, sG[c+5], sBe[c+5]);
            float f6 = fmaf((vb.z-mean)*rstd, sG[c+6], sBe[c+6]);
            float f7 = fmaf((vb.w-mean)*rstd, sG[c+7], sBe[c+7]);
            *(uint4*)(dstrow + g*16) = make_uint4(bfpack(f0,f1), bfpack(f2,f3),
                                                  bfpack(f4,f5), bfpack(f6,f7));
        }
    }
    __syncthreads();

    int ns = wid * 32;
    int br = lane & 7, bg = (lane >> 3) & 1;
    uint32_t bfr[4][4][2];
    #pragma unroll
    for (int nt = 0; nt < 4; nt++)
        #pragma unroll
        for (int kt = 0; kt < 4; kt++)
            ldsm2(bfr[nt][kt], sb + K1_SW_OFF + (ns + nt*8 + br)*144 + bg*16 + kt*32);

    int ag = lane >> 3, ar = lane & 7;
    uint32_t abase = sb + (ar + (ag & 1)*8)*144 + (ag >> 1)*16;
    #pragma unroll 1
    for (int mt = 0; mt < 8; mt++){
        uint32_t af[4][4];
        #pragma unroll
        for (int kt = 0; kt < 4; kt++) ldsm4(af[kt], abase + mt*2304 + kt*32);
        float acc[4][4];
        #pragma unroll
        for (int nt = 0; nt < 4; nt++){ acc[nt][0]=0.f; acc[nt][1]=0.f; acc[nt][2]=0.f; acc[nt][3]=0.f; }
        #pragma unroll
        for (int kt = 0; kt < 4; kt++)
            #pragma unroll
            for (int nt = 0; nt < 4; nt++)
                mma16816(acc[nt], af[kt], bfr[nt][kt]);
        int r0 = mt*16 + (lane >> 2);
        int c0 = ns + (lane & 3)*2;
        __nv_bfloat16* o0 = g_t1b + (P0 + r0)*256;
        __nv_bfloat16* o1 = o0 + 8*256;
        #pragma unroll
        for (int nt = 0; nt < 4; nt++){
            int c = c0 + nt*8;
            st_bf2(o0 + c, acc[nt][0] + sBias[c], acc[nt][1] + sBias[c+1]);
            st_bf2(o1 + c, acc[nt][2] + sBias[c], acc[nt][3] + sBias[c+1]);
        }
    }
}

// ---------------------------------------------------------------------------
// K2: depthwise 3x3 + SimpleGate + GAP partials — vectorized 4ch/half/thread.
// Block = one full 256-px row: 4 segments x 32 threads. Thread owns channel
// quad {4c..4c+3} in both halves (8 channels in, 4 gate channels out).
// ---------------------------------------------------------------------------
__global__ void __launch_bounds__(128) k2_dw_gate(const float* __restrict__ dww, const float* __restrict__ dwb)
{
    int blk = blockIdx.x;             // b*256 + h
    int b   = blk >> 8;
    int h   = blk & 255;
    int seg = threadIdx.x >> 5;       // 0..3 (64-px segment)
    int c4  = threadIdx.x & 31;       // channel quad
    int w0  = seg * 64;
    int cb  = c4 * 4;                 // half0 channel base

    float4 wt0[9], wt1[9];
    #pragma unroll
    for (int i = 0; i < 9; i++){
        wt0[i] = *(const float4*)(dww + i*256 + cb);
        wt1[i] = *(const float4*)(dww + i*256 + 128 + cb);
    }
    float4 bc0 = *(const float4*)(dwb + cb);
    float4 bc1 = *(const float4*)(dwb + 128 + cb);

    const uint2* img = (const uint2*)g_t1b;      // 8B = 4 bf16 ch; row stride 64 uint2/px
    size_t pA = (size_t)(b*256 + h - 1) * 256;   // pixel base of row h-1
    size_t pB = pA + 256, pC = pB + 256;
    bool v0 = (h > 0), v2 = (h < 255);
    const float4 Z = make_float4(0.f,0.f,0.f,0.f);
    #define LD0(pp, wc) bf4(img[((pp) + (size_t)(wc))*64 + c4])
    #define LD1(pp, wc) bf4(img[((pp) + (size_t)(wc))*64 + 32 + c4])

    float4 A0[3][3], A1[3][3];        // [row][wpos]
    {
        int wm = w0 - 1; bool vm = (wm >= 0);
        A0[0][0] = (v0 && vm) ? LD0(pA, wm) : Z;
        A0[1][0] =  vm        ? LD0(pB, wm) : Z;
        A0[2][0] = (v2 && vm) ? LD0(pC, wm) : Z;
        A1[0][0] = (v0 && vm) ? LD1(pA, wm) : Z;
        A1[1][0] =  vm        ? LD1(pB, wm) : Z;
        A1[2][0] = (v2 && vm) ? LD1(pC, wm) : Z;
        A0[0][1] = v0 ? LD0(pA, w0) : Z;
        A0[1][1] =      LD0(pB, w0);
        A0[2][1] = v2 ? LD0(pC, w0) : Z;
        A1[0][1] = v0 ? LD1(pA, w0) : Z;
        A1[1][1] =      LD1(pB, w0);
        A1[2][1] = v2 ? LD1(pC, w0) : Z;
    }
    uint2* yrow = (uint2*)g_yb;       // 8B = 4 gate channels; row stride 32 uint2/px
    float4 gap = Z;
    for (int w = w0; w < w0 + 64; w++){
        int wp = w + 1; bool vp = (wp < 256);
        A0[0][2] = (v0 && vp) ? LD0(pA, wp) : Z;
        A0[1][2] =  vp        ? LD0(pB, wp) : Z;
        A0[2][2] = (v2 && vp) ? LD0(pC, wp) : Z;
        A1[0][2] = (v0 && vp) ? LD1(pA, wp) : Z;
        A1[1][2] =  vp        ? LD1(pB, wp) : Z;
        A1[2][2] = (v2 && vp) ? LD1(pC, wp) : Z;
        float4 a = bc0, c = bc1;
        #pragma unroll
        for (int i = 0; i < 9; i++){
            int rr = i / 3, ww = i % 3;
            a.x = fmaf(A0[rr][ww].x, wt0[i].x, a.x);
            a.y = fmaf(A0[rr][ww].y, wt0[i].y, a.y);
            a.z = fmaf(A0[rr][ww].z, wt0[i].z, a.z);
            a.w = fmaf(A0[rr][ww].w, wt0[i].w, a.w);
            c.x = fmaf(A1[rr][ww].x, wt1[i].x, c.x);
            c.y = fmaf(A1[rr][ww].y, wt1[i].y, c.y);
            c.z = fmaf(A1[rr][ww].z, wt1[i].z, c.z);
            c.w = fmaf(A1[rr][ww].w, wt1[i].w, c.w);
        }
        float4 yv = make_float4(a.x*c.x, a.y*c.y, a.z*c.z, a.w*c.w);
        uint2 pk;
        pk.x = bfpack(yv.x, yv.y);
        pk.y = bfpack(yv.z, yv.w);
        yrow[(pB + (size_t)w)*32 + c4] = pk;
        gap.x += yv.x; gap.y += yv.y; gap.z += yv.z; gap.w += yv.w;
        #pragma unroll
        for (int rr = 0; rr < 3; rr++){
            A0[rr][0] = A0[rr][1]; A0[rr][1] = A0[rr][2];
            A1[rr][0] = A1[rr][1]; A1[rr][1] = A1[rr][2];
        }
    }
    int pid = blk*4 + seg;            // 0..8191; image b owns [b*1024, b*1024+1024)
    *(float4*)(g_part + (size_t)pid*128 + cb) = gap;
    #undef LD0
    #undef LD1
}

// ---------------------------------------------------------------------------
// K3a: GAP partial reduce (128 blocks x 128 threads, 64 rows each)
// ---------------------------------------------------------------------------
__global__ void __launch_bounds__(128) k3a_reduce()
{
    int blk = blockIdx.x;
    int c = threadIdx.x;
    const float* p = g_part + (size_t)blk * 64 * 128 + c;
    float s = 0.f;
    #pragma unroll 16
    for (int i = 0; i < 64; i++) s += p[(size_t)i * 128];
    g_part2[blk*128 + c] = s;
}

// ---------------------------------------------------------------------------
// K3b: final GAP reduce + SCA
// ---------------------------------------------------------------------------
__global__ void k3b_sca(const float* __restrict__ scaw, const float* __restrict__ scab)
{
    __shared__ float smn[128];
    int b = blockIdx.x, c = threadIdx.x;
    float s = 0.f;
    #pragma unroll
    for (int i = 0; i < 16; i++) s += g_part2[(b*16 + i)*128 + c];
    smn[c] = s * (1.f / 65536.f);
    __syncthreads();
    float a = scab[c];
    #pragma unroll 8
    for (int k = 0; k < 128; k++) a = fmaf(smn[k], scaw[k*128 + c], a);
    g_attn[b*128 + c] = a;
}

// ---------------------------------------------------------------------------
// K4a: (y*attn) -> pw2 (128 -> 64) -> x2 = x + .*beta. mma.sync, warp n-slice 8.
// ---------------------------------------------------------------------------
#define K4A_SW_OFF  34816
#define K4A_PAR_OFF 52224
#define K4A_SMEM    53248

__global__ void __launch_bounds__(256) k4a_att_pw2(
    const float* __restrict__ x, const float* __restrict__ b2v, const float* __restrict__ beta)
{
    extern __shared__ char smem[];
    uint32_t sb = smem_u32(smem);
    int tid = threadIdx.x, wid = tid >> 5, lane = tid & 31;
    float* sAttn = (float*)(smem + K4A_PAR_OFF);  // 128
    float* sB2   = sAttn + 128;                   // 64
    float* sBeta = sB2 + 64;                      // 64
    int b = blockIdx.x >> 9;

    {
        int row = tid >> 2, part = tid & 3;
        const uint4* src = (const uint4*)(g_w2t + row*128 + part*32);
        uint4* dst = (uint4*)(smem + K4A_SW_OFF + row*272 + part*64);
        #pragma unroll
        for (int q = 0; q < 4; q++) dst[q] = src[q];
    }
    if (tid < 128) sAttn[tid] = g_attn[b*128 + tid];
    else if (tid < 192) sB2[tid-128] = b2v[tid-128];
    else sBeta[tid-192] = beta[tid-192];
    __syncthreads();

    size_t P0 = (size_t)blockIdx.x * 128;
    {   // stage A = y * attn (bf16, padded rows)
        int row = tid >> 1, half = tid & 1;
        const uint4* src = (const uint4*)(g_yb + (P0 + row)*128 + half*64);
        char* dstrow = smem + row*272 + half*128;
        #pragma unroll
        for (int q = 0; q < 8; q++){
            uint4 raw = src[q];
            const uint32_t* rw = (const uint32_t*)&raw;
            int k0 = half*64 + q*8;
            uint32_t pk[4];
            #pragma unroll
            for (int j = 0; j < 4; j++){
                float2 f = bfunpk(rw[j]);
                f.x *= sAttn[k0 + 2*j]; f.y *= sAttn[k0 + 2*j + 1];
                pk[j] = bfpack(f.x, f.y);
            }
            *(uint4*)(dstrow + q*16) = make_uint4(pk[0], pk[1], pk[2], pk[3]);
        }
    }
    __syncthreads();

    int n0 = wid * 8;
    int br = lane & 7, bg = (lane >> 3) & 1;
    uint32_t bfr[8][2];
    #pragma unroll
    for (int kt = 0; kt < 8; kt++)
        ldsm2(bfr[kt], sb + K4A_SW_OFF + (n0 + br)*272 + bg*16 + kt*32);

    int ag = lane >> 3, ar = lane & 7;
    uint32_t abase = sb + (ar + (ag & 1)*8)*272 + (ag >> 1)*16;
    #pragma unroll 1
    for (int mt = 0; mt < 8; mt++){
        uint32_t af[8][4];
        #pragma unroll
        for (int kt = 0; kt < 8; kt++) ldsm4(af[kt], abase + mt*4352 + kt*32);
        float acc[4] = {0.f, 0.f, 0.f, 0.f};
        #pragma unroll
        for (int kt = 0; kt < 8; kt++) mma16816(acc, af[kt], bfr[kt]);
        int r0 = mt*16 + (lane >> 2);
        int c0 = n0 + (lane & 3)*2;
        float2 xv0 = *(const float2*)(x + (P0 + r0)*64 + c0);
        float2 xv1 = *(const float2*)(x + (P0 + r0 + 8)*64 + c0);
        float2 o0, o1;
        o0.x = fmaf(acc[0] + sB2[c0],   sBeta[c0],   xv0.x);
        o0.y = fmaf(acc[1] + sB2[c0+1], sBeta[c0+1], xv0.y);
        o1.x = fmaf(acc[2] + sB2[c0],   sBeta[c0],   xv1.x);
        o1.y = fmaf(acc[3] + sB2[c0+1], sBeta[c0+1], xv1.y);
        *(float2*)(g_x2 + (P0 + r0)*64 + c0)     = o0;
        *(float2*)(g_x2 + (P0 + r0 + 8)*64 + c0) = o1;
    }
}

// ---------------------------------------------------------------------------
// K4b (fused): LN2 -> pw3 -> SimpleGate (smem) -> pw4 -> out.
// ---------------------------------------------------------------------------
#define K4B_SW3_OFF  18432
#define K4B_GT_OFF   55296
#define K4B_SW4_OFF  90112
#define K4B_PAR_OFF  107520
#define K4B_SMEM     109568

__global__ void __launch_bounds__(256) k4b_fused(
    const float* __restrict__ b3v, const float* __restrict__ g2, const float* __restrict__ bb2,
    const float* __restrict__ b4v, const float* __restrict__ gamma, float* __restrict__ out)
{
    extern __shared__ char smem[];
    uint32_t sb = smem_u32(smem);
    int tid = threadIdx.x, wid = tid >> 5, lane = tid & 31;
    float* sB3 = (float*)(smem + K4B_PAR_OFF);    // 256 (interleaved)
    float* sG  = sB3 + 256;                       // 64
    float* sBe = sG + 64;                         // 64
    float* sB4 = sBe + 64;                        // 64
    float* sGa = sB4 + 64;                        // 64

    {
        const uint4* src = (const uint4*)(g_w3t + tid*64);
        uint4* dst = (uint4*)(smem + K4B_SW3_OFF + tid*144);
        #pragma unroll
        for (int q = 0; q < 8; q++) dst[q] = src[q];
    }
    {
        int row = tid >> 2, part = tid & 3;
        const uint4* src = (const uint4*)(g_w4t + row*128 + part*32);
        uint4* dst = (uint4*)(smem + K4B_SW4_OFF + row*272 + part*64);
        #pragma unroll
        for (int q = 0; q < 4; q++) dst[q] = src[q];
    }
    sB3[tid] = b3v[(tid & 1)*128 + (tid >> 1)];
    if (tid < 64){ sG[tid] = g2[tid]; sBe[tid] = bb2[tid]; }
    else if (tid < 128) sB4[tid-64] = b4v[tid-64];
    else if (tid < 192) sGa[tid-128] = gamma[tid-128];
    __syncthreads();

    size_t P0 = (size_t)blockIdx.x * 128;
    {   // LN2 of g_x2 -> A tile
        int px = tid >> 1, half = tid & 1;
        const float4* xp = (const float4*)(g_x2 + (P0 + px) * 64 + half * 32);
        float4 v[8];
        #pragma unroll
        for (int q = 0; q < 8; q++) v[q] = xp[q];
        float s = 0.f, ss = 0.f;
        #pragma unroll
        for (int q = 0; q < 8; q++){
            float4 t = v[q];
            s += t.x + t.y + t.z + t.w;
            ss = fmaf(t.x,t.x, fmaf(t.y,t.y, fmaf(t.z,t.z, fmaf(t.w,t.w, ss))));
        }
        s  += __shfl_xor_sync(0xffffffffu, s, 1);
        ss += __shfl_xor_sync(0xffffffffu, ss, 1);
        float mean = s * (1.f/64.f);
        float var  = fmaf(-mean, mean, ss * (1.f/64.f));
        float rstd = rsqrtf(var + EPSV);
        char* dstrow = smem + px*144 + half*64;
        #pragma unroll
        for (int g = 0; g < 4; g++){
            float4 va = v[2*g], vb = v[2*g+1];
            int c = half*32 + g*8;
            float f0 = fmaf((va.x-mean)*rstd, sG[c+0], sBe[c+0]);
            float f1 = fmaf((va.y-mean)*rstd, sG[c+1], sBe[c+1]);
            float f2 = fmaf((va.z-mean)*rstd, sG[c+2], sBe[c+2]);
            float f3 = fmaf((va.w-mean)*rstd, sG[c+3], sBe[c+3]);
            float f4 = fmaf((vb.x-mean)*rstd, sG[c+4], sBe[c+4]);
            float f5 = fmaf((vb.y-mean)*rstd, sG[c+5], sBe[c+5]);
            float f6 = fmaf((vb.z-mean)*rstd, sG[c+6], sBe[c+6]);
            float f7 = fmaf((vb.w-mean)*rstd, sG[c+7], sBe[c+7]);
            *(uint4*)(dstrow + g*16) = make_uint4(bfpack(f0,f1), bfpack(f2,f3),
                                                  bfpack(f4,f5), bfpack(f6,f7));
        }
    }
    __syncthreads();

    {   // phase 1: pw3 GEMM + gate -> smem
        int ns = wid * 32;
        int br = lane & 7, bg = (lane >> 3) & 1;
        uint32_t bfr[4][4][2];
        #pragma unroll
        for (int nt = 0; nt < 4; nt++)
            #pragma unroll
            for (int kt = 0; kt < 4; kt++)
                ldsm2(bfr[nt][kt], sb + K4B_SW3_OFF + (ns + nt*8 + br)*144 + bg*16 + kt*32);

        int ag = lane >> 3, ar = lane & 7;
        uint32_t abase = sb + (ar + (ag & 1)*8)*144 + (ag >> 1)*16;
        #pragma unroll 1
        for (int mt = 0; mt < 8; mt++){
            uint32_t af[4][4];
            #pragma unroll
            for (int kt = 0; kt < 4; kt++) ldsm4(af[kt], abase + mt*2304 + kt*32);
            float acc[4][4];
            #pragma unroll
            for (int nt = 0; nt < 4; nt++){ acc[nt][0]=0.f; acc[nt][1]=0.f; acc[nt][2]=0.f; acc[nt][3]=0.f; }
            #pragma unroll
            for (int kt = 0; kt < 4; kt++)
                #pragma unroll
                for (int nt = 0; nt < 4; nt++)
                    mma16816(acc[nt], af[kt], bfr[nt][kt]);
            int r0 = mt*16 + (lane >> 2);
            int c0 = ns + (lane & 3)*2;
            char* g0 = smem + K4B_GT_OFF + r0*272;
            char* g1 = g0 + 8*272;
            #pragma unroll
            for (int nt = 0; nt < 4; nt++){
                int c = c0 + nt*8;
                float ga = (acc[nt][0] + sB3[c]) * (acc[nt][1] + sB3[c+1]);
                float gb = (acc[nt][2] + sB3[c]) * (acc[nt][3] + sB3[c+1]);
                *(__nv_bfloat16*)(g0 + (c >> 1)*2) = __float2bfloat16(ga);
                *(__nv_bfloat16*)(g1 + (c >> 1)*2) = __float2bfloat16(gb);
            }
        }
    }
    __syncthreads();

    {   // phase 2: pw4 GEMM + gamma residual -> out
        int n0 = wid * 8;
        int br = lane & 7, bg = (lane >> 3) & 1;
        uint32_t bfr[8][2];
        #pragma unroll
        for (int kt = 0; kt < 8; kt++)
            ldsm2(bfr[kt], sb + K4B_SW4_OFF + (n0 + br)*272 + bg*16 + kt*32);

        int ag = lane >> 3, ar = lane & 7;
        uint32_t abase = sb + K4B_GT_OFF + (ar + (ag & 1)*8)*272 + (ag >> 1)*16;
        #pragma unroll 1
        for (int mt = 0; mt < 8; mt++){
            uint32_t af[8][4];
            #pragma unroll
            for (int kt = 0; kt < 8; kt++) ldsm4(af[kt], abase + mt*4352 + kt*32);
            float acc[4] = {0.f, 0.f, 0.f, 0.f};
            #pragma unroll
            for (int kt = 0; kt < 8; kt++) mma16816(acc, af[kt], bfr[kt]);
            int r0 = mt*16 + (lane >> 2);
            int c0 = n0 + (lane & 3)*2;
            float2 xv0 = *(const float2*)(g_x2 + (P0 + r0)*64 + c0);
            float2 xv1 = *(const float2*)(g_x2 + (P0 + r0 + 8)*64 + c0);
            float2 o0, o1;
            o0.x = fmaf(acc[0] + sB4[c0],   sGa[c0],   xv0.x);
            o0.y = fmaf(acc[1] + sB4[c0+1], sGa[c0+1], xv0.y);
            o1.x = fmaf(acc[2] + sB4[c0],   sGa[c0],   xv1.x);
            o1.y = fmaf(acc[3] + sB4[c0+1], sGa[c0+1], xv1.y);
            *(float2*)(out + (P0 + r0)*64 + c0)     = o0;
            *(float2*)(out + (P0 + r0 + 8)*64 + c0) = o1;
        }
    }
}

// ---------------------------------------------------------------------------
extern "C" void kernel_launch(void* const* d_in, const int* in_sizes, int n_in,
                              void* d_out, int out_size)
{
    const float* x    = (const float*)d_in[0];
    const float* ln1g = (const float*)d_in[1];
    const float* ln1b = (const float*)d_in[2];
    const float* pw1w = (const float*)d_in[3];
    const float* pw1b = (const float*)d_in[4];
    const float* dww  = (const float*)d_in[5];
    const float* dwb  = (const float*)d_in[6];
    const float* scaw = (const float*)d_in[7];
    const float* scab = (const float*)d_in[8];
    const float* pw2w = (const float*)d_in[9];
    const float* pw2b = (const float*)d_in[10];
    const float* beta = (const float*)d_in[11];
    const float* ln2g = (const float*)d_in[12];
    const float* ln2b = (const float*)d_in[13];
    const float* pw3w = (const float*)d_in[14];
    const float* pw3b = (const float*)d_in[15];
    const float* pw4w = (const float*)d_in[16];
    const float* pw4b = (const float*)d_in[17];
    const float* gam  = (const float*)d_in[18];
    float* out = (float*)d_out;

    cudaFuncSetAttribute(k1_ln_pw1,   cudaFuncAttributeMaxDynamicSharedMemorySize, K1_SMEM);
    cudaFuncSetAttribute(k4a_att_pw2, cudaFuncAttributeMaxDynamicSharedMemorySize, K4A_SMEM);
    cudaFuncSetAttribute(k4b_fused,   cudaFuncAttributeMaxDynamicSharedMemorySize, K4B_SMEM);

    k0_prep    <<<192, 256>>>(pw1w, pw2w, pw3w, pw4w);
    k1_ln_pw1  <<<NPIX/128, 256, K1_SMEM>>>(x, ln1g, ln1b, pw1b);
    k2_dw_gate <<<2048, 128>>>(dww, dwb);
    k3a_reduce <<<128, 128>>>();
    k3b_sca    <<<BB, 128>>>(scaw, scab);
    k4a_att_pw2<<<NPIX/128, 256, K4A_SMEM>>>(x, pw2b, beta);
    k4b_fused  <<<NPIX/128, 256, K4B_SMEM>>>(pw3b, ln2g, ln2b, pw4b, gam, out);
}